// round 2
// baseline (speedup 1.0000x reference)
#include <cuda_runtime.h>

// Problem constants
constexpr int NE   = 1024;   // n_embd
constexpr int NH   = 16;     // heads
constexpr int DK   = 64;     // head dim
constexpr int BB   = 2;      // batch
constexpr int TT   = 2048;   // seq len
constexpr int MTOT = BB * TT;  // 4096 rows

// Scratch (allocation-free rule: __device__ globals)
__device__ float g_q[BB * NH * TT * DK];
__device__ float g_k[BB * NH * TT * DK];
__device__ float g_v[BB * NH * TT * DK];
__device__ float g_y[BB * TT * NE];

// ---------------------------------------------------------------------------
// Tiled SGEMM: out[m, n] = sum_k X[m, k] * W[n, k] + bias[n]
// BM=BN=64, BK=16, 256 threads, 4x4 register micro-tile per thread.
// SPLIT=true scatters output into head-major [b, h, t, d] layout.
// ---------------------------------------------------------------------------
template <bool SPLIT>
__global__ __launch_bounds__(256)
void linear_kernel(const float* __restrict__ X, const float* __restrict__ W,
                   const float* __restrict__ bias, float* __restrict__ out)
{
    __shared__ float Xs[16][68];   // [k][m], padded to avoid STS conflicts
    __shared__ float Ws[16][68];   // [k][n]

    const int bn  = blockIdx.x * 64;
    const int bm  = blockIdx.y * 64;
    const int tid = threadIdx.x;
    const int tx  = tid & 15;      // 0..15 -> n
    const int ty  = tid >> 4;      // 0..15 -> m

    float acc[4][4] = {};

    for (int k0 = 0; k0 < NE; k0 += 16) {
        #pragma unroll
        for (int i = 0; i < 4; i++) {
            int idx = tid + i * 256;          // 0..1023
            int m   = idx >> 4;
            int k   = idx & 15;
            Xs[k][m] = X[(bm + m) * NE + k0 + k];
            Ws[k][m] = W[(bn + m) * NE + k0 + k];
        }
        __syncthreads();

        #pragma unroll
        for (int k = 0; k < 16; k++) {
            float4 a = *(const float4*)&Xs[k][ty * 4];
            float4 b = *(const float4*)&Ws[k][tx * 4];
            float av[4] = {a.x, a.y, a.z, a.w};
            float bv[4] = {b.x, b.y, b.z, b.w};
            #pragma unroll
            for (int i = 0; i < 4; i++)
                #pragma unroll
                for (int j = 0; j < 4; j++)
                    acc[i][j] += av[i] * bv[j];
        }
        __syncthreads();
    }

    #pragma unroll
    for (int i = 0; i < 4; i++) {
        int m = bm + ty * 4 + i;
        #pragma unroll
        for (int j = 0; j < 4; j++) {
            int n = bn + tx * 4 + j;
            float v = acc[i][j] + bias[n];
            if (SPLIT) {
                int b = m >> 11;          // m / TT
                int t = m & (TT - 1);
                int h = n >> 6;           // n / DK
                int d = n & 63;
                out[(((b * NH + h) * TT + t) << 6) + d] = v;
            } else {
                out[m * NE + n] = v;
            }
        }
    }
}

// ---------------------------------------------------------------------------
// Flash-attention-style causal attention (fp32).
// Grid: (TT/128, NH, BB). One thread = one query row; q/o in registers.
// K/V staged in 64-row smem tiles; keys processed in groups of 8 with
// online softmax in exp2 domain (1/sqrt(dk)*log2(e) folded into q).
// ---------------------------------------------------------------------------
__global__ __launch_bounds__(128)
void attn_kernel(const float* __restrict__ Q, const float* __restrict__ K,
                 const float* __restrict__ V, float* __restrict__ Y)
{
    __shared__ float Ks[64][64];
    __shared__ float Vs[64][64];

    const int qt  = blockIdx.x;
    const int h   = blockIdx.y;
    const int b   = blockIdx.z;
    const int row = qt * 128 + threadIdx.x;
    const int base = (b * NH + h) * TT;     // row base in head-major layout

    const float* qptr = Q + (base + row) * DK;

    float q[64];
    #pragma unroll
    for (int i = 0; i < 16; i++)
        ((float4*)q)[i] = ((const float4*)qptr)[i];

    const float SC = 0.125f * 1.44269504f;  // 1/sqrt(64) * log2(e)
    #pragma unroll
    for (int i = 0; i < 64; i++) q[i] *= SC;

    float o[64] = {};
    float mcur = -1e30f;
    float l = 0.f;

    const int nkb = 2 * qt + 2;  // key blocks intersecting causal region
    for (int kb = 0; kb < nkb; kb++) {
        const float* kptr = K + (base + kb * 64) * DK;
        const float* vptr = V + (base + kb * 64) * DK;

        __syncthreads();
        #pragma unroll
        for (int i = 0; i < 8; i++) {
            int idx = threadIdx.x + i * 128;   // 1024 float4s per tile
            ((float4*)Ks)[idx] = ((const float4*)kptr)[idx];
            ((float4*)Vs)[idx] = ((const float4*)vptr)[idx];
        }
        __syncthreads();

        const int kbase = kb * 64;

        #pragma unroll 1
        for (int g = 0; g < 8; g++) {
            float s[8];
            float gmax = -1e30f;

            // QK^T for 8 keys (4 partial sums per key for ILP)
            #pragma unroll
            for (int jj = 0; jj < 8; jj++) {
                const int j = g * 8 + jj;
                float p0 = 0.f, p1 = 0.f, p2 = 0.f, p3 = 0.f;
                #pragma unroll
                for (int d4 = 0; d4 < 16; d4++) {
                    float4 kv = *(const float4*)&Ks[j][d4 * 4];
                    p0 += q[d4 * 4 + 0] * kv.x;
                    p1 += q[d4 * 4 + 1] * kv.y;
                    p2 += q[d4 * 4 + 2] * kv.z;
                    p3 += q[d4 * 4 + 3] * kv.w;
                }
                float sj = (p0 + p1) + (p2 + p3);
                if (kbase + j > row) sj = -1e30f;  // causal mask
                s[jj] = sj;
                gmax  = fmaxf(gmax, sj);
            }

            // Online softmax group update
            float mnew = fmaxf(mcur, gmax);
            float corr = exp2f(mcur - mnew);
            l *= corr;
            #pragma unroll
            for (int d = 0; d < 64; d++) o[d] *= corr;
            mcur = mnew;

            // P @ V for 8 keys
            #pragma unroll
            for (int jj = 0; jj < 8; jj++) {
                const int j = g * 8 + jj;
                float p = exp2f(s[jj] - mnew);
                l += p;
                #pragma unroll
                for (int d4 = 0; d4 < 16; d4++) {
                    float4 vv = *(const float4*)&Vs[j][d4 * 4];
                    o[d4 * 4 + 0] += p * vv.x;
                    o[d4 * 4 + 1] += p * vv.y;
                    o[d4 * 4 + 2] += p * vv.z;
                    o[d4 * 4 + 3] += p * vv.w;
                }
            }
        }
    }

    const float inv = 1.f / l;
    float* yptr = Y + (b * TT + row) * NE + h * DK;
    #pragma unroll
    for (int d4 = 0; d4 < 16; d4++) {
        float4 ov;
        ov.x = o[d4 * 4 + 0] * inv;
        ov.y = o[d4 * 4 + 1] * inv;
        ov.z = o[d4 * 4 + 2] * inv;
        ov.w = o[d4 * 4 + 3] * inv;
        ((float4*)yptr)[d4] = ov;
    }
}

// ---------------------------------------------------------------------------
extern "C" void kernel_launch(void* const* d_in, const int* in_sizes, int n_in,
                              void* d_out, int out_size)
{
    const float* x  = (const float*)d_in[0];
    const float* Wq = (const float*)d_in[1];
    const float* bq = (const float*)d_in[2];
    const float* Wk = (const float*)d_in[3];
    const float* bk = (const float*)d_in[4];
    const float* Wv = (const float*)d_in[5];
    const float* bv = (const float*)d_in[6];
    const float* Wo = (const float*)d_in[7];
    const float* bo = (const float*)d_in[8];
    float* out = (float*)d_out;

    float *q, *k, *v, *y;
    cudaGetSymbolAddress((void**)&q, g_q);
    cudaGetSymbolAddress((void**)&k, g_k);
    cudaGetSymbolAddress((void**)&v, g_v);
    cudaGetSymbolAddress((void**)&y, g_y);

    dim3 blk(256);
    dim3 gproj(NE / 64, MTOT / 64);  // (16, 64)

    linear_kernel<true><<<gproj, blk>>>(x, Wq, bq, q);
    linear_kernel<true><<<gproj, blk>>>(x, Wk, bk, k);
    linear_kernel<true><<<gproj, blk>>>(x, Wv, bv, v);

    attn_kernel<<<dim3(TT / 128, NH, BB), 128>>>(q, k, v, y);

    linear_kernel<false><<<gproj, blk>>>(y, Wo, bo, out);
}

// round 3
// speedup vs baseline: 1.5704x; 1.5704x over previous
#include <cuda_runtime.h>
#include <cstdint>

// Problem constants
constexpr int NE   = 1024;   // n_embd
constexpr int NH   = 16;     // heads
constexpr int DK   = 64;     // head dim
constexpr int BB   = 2;      // batch
constexpr int TT   = 2048;   // seq len
constexpr int MTOT = BB * TT;  // 4096 rows

// Scratch (allocation-free rule: __device__ globals)
__device__ float g_q[BB * NH * TT * DK];
__device__ float g_k[BB * NH * TT * DK];
__device__ float g_v[BB * NH * TT * DK];
__device__ float g_y[BB * TT * NE];

// ---------------------------------------------------------------------------
// fp32 -> tf32 (round to nearest)
// ---------------------------------------------------------------------------
__device__ __forceinline__ uint32_t f2tf(float f) {
    uint32_t u;
    asm("cvt.rna.tf32.f32 %0, %1;" : "=r"(u) : "f"(f));
    return u;
}

__device__ __forceinline__ void mma_tf32(float c[4], const uint32_t a[4], const uint32_t b[2]) {
    asm volatile(
        "mma.sync.aligned.m16n8k8.row.col.f32.tf32.tf32.f32 "
        "{%0,%1,%2,%3}, {%4,%5,%6,%7}, {%8,%9}, {%0,%1,%2,%3};\n"
        : "+f"(c[0]), "+f"(c[1]), "+f"(c[2]), "+f"(c[3])
        : "r"(a[0]), "r"(a[1]), "r"(a[2]), "r"(a[3]), "r"(b[0]), "r"(b[1]));
}

// ---------------------------------------------------------------------------
// Tensor-core tf32 GEMM: out[m,n] = sum_k X[m,k]*W[n,k] + bias[n]
// Block tile 128x128, BK=16, 256 threads = 8 warps (2m x 4n), warp tile 64x32.
// Double-buffered smem with fp32->tf32 conversion at store time.
// Smem row stride = 20 words -> conflict-free fragment loads.
// SPLIT=true scatters into head-major [b,h,t,d].
// ---------------------------------------------------------------------------
template <bool SPLIT>
__global__ __launch_bounds__(256, 2)
void linear_tc(const float* __restrict__ X, const float* __restrict__ W,
               const float* __restrict__ bias, float* __restrict__ out)
{
    __shared__ uint32_t Xs[2][128 * 20];
    __shared__ uint32_t Ws[2][128 * 20];

    const int bn   = blockIdx.x * 128;
    const int bm   = blockIdx.y * 128;
    const int tid  = threadIdx.x;
    const int lane = tid & 31;
    const int wid  = tid >> 5;
    const int wm   = wid >> 2;      // 0..1
    const int wn   = wid & 3;       // 0..3

    // Per-thread stage-load geometry: 512 float4 per matrix per stage,
    // thread handles rows r0 and r0+64, 4 consecutive floats each.
    const int r0 = tid >> 2;
    const int c0 = (tid & 3) * 4;

    float4 xa, xb, wa, wb;

    auto LOAD = [&](int k0) {
        xa = *(const float4*)&X[(bm + r0)      * NE + k0 + c0];
        xb = *(const float4*)&X[(bm + r0 + 64) * NE + k0 + c0];
        wa = *(const float4*)&W[(bn + r0)      * NE + k0 + c0];
        wb = *(const float4*)&W[(bn + r0 + 64) * NE + k0 + c0];
    };

    auto STS = [&](int buf) {
        uint32_t* p;
        p = &Xs[buf][r0 * 20 + c0];
        p[0] = f2tf(xa.x); p[1] = f2tf(xa.y); p[2] = f2tf(xa.z); p[3] = f2tf(xa.w);
        p = &Xs[buf][(r0 + 64) * 20 + c0];
        p[0] = f2tf(xb.x); p[1] = f2tf(xb.y); p[2] = f2tf(xb.z); p[3] = f2tf(xb.w);
        p = &Ws[buf][r0 * 20 + c0];
        p[0] = f2tf(wa.x); p[1] = f2tf(wa.y); p[2] = f2tf(wa.z); p[3] = f2tf(wa.w);
        p = &Ws[buf][(r0 + 64) * 20 + c0];
        p[0] = f2tf(wb.x); p[1] = f2tf(wb.y); p[2] = f2tf(wb.z); p[3] = f2tf(wb.w);
    };

    float acc[4][4][4] = {};

    auto MMA_STAGE = [&](int buf) {
        #pragma unroll
        for (int kk = 0; kk < 16; kk += 8) {
            uint32_t a[4][4], b[4][2];
            #pragma unroll
            for (int i = 0; i < 4; i++) {
                int r = wm * 64 + i * 16 + (lane >> 2);
                const uint32_t* p = &Xs[buf][r * 20 + kk + (lane & 3)];
                a[i][0] = p[0];
                a[i][1] = p[8 * 20];
                a[i][2] = p[4];
                a[i][3] = p[8 * 20 + 4];
            }
            #pragma unroll
            for (int j = 0; j < 4; j++) {
                int c = wn * 32 + j * 8 + (lane >> 2);
                const uint32_t* p = &Ws[buf][c * 20 + kk + (lane & 3)];
                b[j][0] = p[0];
                b[j][1] = p[4];
            }
            #pragma unroll
            for (int i = 0; i < 4; i++)
                #pragma unroll
                for (int j = 0; j < 4; j++)
                    mma_tf32(acc[i][j], a[i], b[j]);
        }
    };

    LOAD(0);
    STS(0);
    __syncthreads();

    int cur = 0;
    for (int k0 = 16; k0 < NE; k0 += 16) {
        LOAD(k0);
        MMA_STAGE(cur);
        STS(cur ^ 1);
        __syncthreads();
        cur ^= 1;
    }
    MMA_STAGE(cur);

    // Epilogue: bias add + store (float2 per accumulator pair)
    #pragma unroll
    for (int i = 0; i < 4; i++) {
        const int m = bm + wm * 64 + i * 16 + (lane >> 2);
        #pragma unroll
        for (int j = 0; j < 4; j++) {
            const int n = bn + wn * 32 + j * 8 + (lane & 3) * 2;
            const float b0v = bias[n], b1v = bias[n + 1];
            float2 v0 = make_float2(acc[i][j][0] + b0v, acc[i][j][1] + b1v);
            float2 v1 = make_float2(acc[i][j][2] + b0v, acc[i][j][3] + b1v);
            if (SPLIT) {
                const int b  = m >> 11;
                const int t  = m & (TT - 1);
                const int t2 = (m + 8) & (TT - 1);
                const int h  = n >> 6;
                const int d  = n & 63;
                *(float2*)&out[(((b * NH + h) * TT + t)  << 6) + d] = v0;
                *(float2*)&out[(((b * NH + h) * TT + t2) << 6) + d] = v1;
            } else {
                *(float2*)&out[m * NE + n]       = v0;
                *(float2*)&out[(m + 8) * NE + n] = v1;
            }
        }
    }
}

// ---------------------------------------------------------------------------
// Flash-attention-style causal attention (fp32) — unchanged from R1.
// ---------------------------------------------------------------------------
__global__ __launch_bounds__(128)
void attn_kernel(const float* __restrict__ Q, const float* __restrict__ K,
                 const float* __restrict__ V, float* __restrict__ Y)
{
    __shared__ float Ks[64][64];
    __shared__ float Vs[64][64];

    const int qt  = blockIdx.x;
    const int h   = blockIdx.y;
    const int b   = blockIdx.z;
    const int row = qt * 128 + threadIdx.x;
    const int base = (b * NH + h) * TT;

    const float* qptr = Q + (base + row) * DK;

    float q[64];
    #pragma unroll
    for (int i = 0; i < 16; i++)
        ((float4*)q)[i] = ((const float4*)qptr)[i];

    const float SC = 0.125f * 1.44269504f;  // 1/sqrt(64) * log2(e)
    #pragma unroll
    for (int i = 0; i < 64; i++) q[i] *= SC;

    float o[64] = {};
    float mcur = -1e30f;
    float l = 0.f;

    const int nkb = 2 * qt + 2;
    for (int kb = 0; kb < nkb; kb++) {
        const float* kptr = K + (base + kb * 64) * DK;
        const float* vptr = V + (base + kb * 64) * DK;

        __syncthreads();
        #pragma unroll
        for (int i = 0; i < 8; i++) {
            int idx = threadIdx.x + i * 128;
            ((float4*)Ks)[idx] = ((const float4*)kptr)[idx];
            ((float4*)Vs)[idx] = ((const float4*)vptr)[idx];
        }
        __syncthreads();

        const int kbase = kb * 64;

        #pragma unroll 1
        for (int g = 0; g < 8; g++) {
            float s[8];
            float gmax = -1e30f;

            #pragma unroll
            for (int jj = 0; jj < 8; jj++) {
                const int j = g * 8 + jj;
                float p0 = 0.f, p1 = 0.f, p2 = 0.f, p3 = 0.f;
                #pragma unroll
                for (int d4 = 0; d4 < 16; d4++) {
                    float4 kv = *(const float4*)&Ks[j][d4 * 4];
                    p0 += q[d4 * 4 + 0] * kv.x;
                    p1 += q[d4 * 4 + 1] * kv.y;
                    p2 += q[d4 * 4 + 2] * kv.z;
                    p3 += q[d4 * 4 + 3] * kv.w;
                }
                float sj = (p0 + p1) + (p2 + p3);
                if (kbase + j > row) sj = -1e30f;
                s[jj] = sj;
                gmax  = fmaxf(gmax, sj);
            }

            float mnew = fmaxf(mcur, gmax);
            float corr = exp2f(mcur - mnew);
            l *= corr;
            #pragma unroll
            for (int d = 0; d < 64; d++) o[d] *= corr;
            mcur = mnew;

            #pragma unroll
            for (int jj = 0; jj < 8; jj++) {
                const int j = g * 8 + jj;
                float p = exp2f(s[jj] - mnew);
                l += p;
                #pragma unroll
                for (int d4 = 0; d4 < 16; d4++) {
                    float4 vv = *(const float4*)&Vs[j][d4 * 4];
                    o[d4 * 4 + 0] += p * vv.x;
                    o[d4 * 4 + 1] += p * vv.y;
                    o[d4 * 4 + 2] += p * vv.z;
                    o[d4 * 4 + 3] += p * vv.w;
                }
            }
        }
    }

    const float inv = 1.f / l;
    float* yptr = Y + (b * TT + row) * NE + h * DK;
    #pragma unroll
    for (int d4 = 0; d4 < 16; d4++) {
        float4 ov;
        ov.x = o[d4 * 4 + 0] * inv;
        ov.y = o[d4 * 4 + 1] * inv;
        ov.z = o[d4 * 4 + 2] * inv;
        ov.w = o[d4 * 4 + 3] * inv;
        ((float4*)yptr)[d4] = ov;
    }
}

// ---------------------------------------------------------------------------
extern "C" void kernel_launch(void* const* d_in, const int* in_sizes, int n_in,
                              void* d_out, int out_size)
{
    const float* x  = (const float*)d_in[0];
    const float* Wq = (const float*)d_in[1];
    const float* bq = (const float*)d_in[2];
    const float* Wk = (const float*)d_in[3];
    const float* bk = (const float*)d_in[4];
    const float* Wv = (const float*)d_in[5];
    const float* bv = (const float*)d_in[6];
    const float* Wo = (const float*)d_in[7];
    const float* bo = (const float*)d_in[8];
    float* out = (float*)d_out;

    float *q, *k, *v, *y;
    cudaGetSymbolAddress((void**)&q, g_q);
    cudaGetSymbolAddress((void**)&k, g_k);
    cudaGetSymbolAddress((void**)&v, g_v);
    cudaGetSymbolAddress((void**)&y, g_y);

    dim3 blk(256);
    dim3 gproj(NE / 128, MTOT / 128);  // (8, 32)

    linear_tc<true><<<gproj, blk>>>(x, Wq, bq, q);
    linear_tc<true><<<gproj, blk>>>(x, Wk, bk, k);
    linear_tc<true><<<gproj, blk>>>(x, Wv, bv, v);

    attn_kernel<<<dim3(TT / 128, NH, BB), 128>>>(q, k, v, y);

    linear_tc<false><<<gproj, blk>>>(y, Wo, bo, out);
}

// round 5
// speedup vs baseline: 3.1420x; 2.0008x over previous
#include <cuda_runtime.h>
#include <cstdint>

// Problem constants
constexpr int NE   = 1024;   // n_embd
constexpr int NH   = 16;     // heads
constexpr int DK   = 64;     // head dim
constexpr int BB   = 2;      // batch
constexpr int TT   = 2048;   // seq len
constexpr int MTOT = BB * TT;  // 4096 rows

// Scratch (allocation-free rule: __device__ globals)
__device__ float g_q[BB * NH * TT * DK];
__device__ float g_k[BB * NH * TT * DK];
__device__ float g_v[BB * NH * TT * DK];
__device__ float g_y[BB * TT * NE];

// ---------------------------------------------------------------------------
// helpers
// ---------------------------------------------------------------------------
__device__ __forceinline__ uint32_t f2tf(float f) {
    uint32_t u;
    asm("cvt.rna.tf32.f32 %0, %1;" : "=r"(u) : "f"(f));
    return u;
}

__device__ __forceinline__ float ex2(float x) {
    float r;
    asm("ex2.approx.f32 %0, %1;" : "=f"(r) : "f"(x));
    return r;
}

__device__ __forceinline__ void mma_tf32(float c[4], const uint32_t a[4], const uint32_t b[2]) {
    asm volatile(
        "mma.sync.aligned.m16n8k8.row.col.f32.tf32.tf32.f32 "
        "{%0,%1,%2,%3}, {%4,%5,%6,%7}, {%8,%9}, {%0,%1,%2,%3};\n"
        : "+f"(c[0]), "+f"(c[1]), "+f"(c[2]), "+f"(c[3])
        : "r"(a[0]), "r"(a[1]), "r"(a[2]), "r"(a[3]), "r"(b[0]), "r"(b[1]));
}

// ---------------------------------------------------------------------------
// Tensor-core tf32 GEMM: out[m,n] = sum_k X[m,k]*W[n,k] + bias[n]
// (unchanged from R2)
// ---------------------------------------------------------------------------
template <bool SPLIT>
__global__ __launch_bounds__(256, 2)
void linear_tc(const float* __restrict__ X, const float* __restrict__ W,
               const float* __restrict__ bias, float* __restrict__ out)
{
    __shared__ uint32_t Xs[2][128 * 20];
    __shared__ uint32_t Ws[2][128 * 20];

    const int bn   = blockIdx.x * 128;
    const int bm   = blockIdx.y * 128;
    const int tid  = threadIdx.x;
    const int lane = tid & 31;
    const int wid  = tid >> 5;
    const int wm   = wid >> 2;
    const int wn   = wid & 3;

    const int r0 = tid >> 2;
    const int c0 = (tid & 3) * 4;

    float4 xa, xb, wa, wb;

    auto LOAD = [&](int k0) {
        xa = *(const float4*)&X[(bm + r0)      * NE + k0 + c0];
        xb = *(const float4*)&X[(bm + r0 + 64) * NE + k0 + c0];
        wa = *(const float4*)&W[(bn + r0)      * NE + k0 + c0];
        wb = *(const float4*)&W[(bn + r0 + 64) * NE + k0 + c0];
    };

    auto STS = [&](int buf) {
        uint32_t* p;
        p = &Xs[buf][r0 * 20 + c0];
        p[0] = f2tf(xa.x); p[1] = f2tf(xa.y); p[2] = f2tf(xa.z); p[3] = f2tf(xa.w);
        p = &Xs[buf][(r0 + 64) * 20 + c0];
        p[0] = f2tf(xb.x); p[1] = f2tf(xb.y); p[2] = f2tf(xb.z); p[3] = f2tf(xb.w);
        p = &Ws[buf][r0 * 20 + c0];
        p[0] = f2tf(wa.x); p[1] = f2tf(wa.y); p[2] = f2tf(wa.z); p[3] = f2tf(wa.w);
        p = &Ws[buf][(r0 + 64) * 20 + c0];
        p[0] = f2tf(wb.x); p[1] = f2tf(wb.y); p[2] = f2tf(wb.z); p[3] = f2tf(wb.w);
    };

    float acc[4][4][4] = {};

    auto MMA_STAGE = [&](int buf) {
        #pragma unroll
        for (int kk = 0; kk < 16; kk += 8) {
            uint32_t a[4][4], b[4][2];
            #pragma unroll
            for (int i = 0; i < 4; i++) {
                int r = wm * 64 + i * 16 + (lane >> 2);
                const uint32_t* p = &Xs[buf][r * 20 + kk + (lane & 3)];
                a[i][0] = p[0];
                a[i][1] = p[8 * 20];
                a[i][2] = p[4];
                a[i][3] = p[8 * 20 + 4];
            }
            #pragma unroll
            for (int j = 0; j < 4; j++) {
                int c = wn * 32 + j * 8 + (lane >> 2);
                const uint32_t* p = &Ws[buf][c * 20 + kk + (lane & 3)];
                b[j][0] = p[0];
                b[j][1] = p[4];
            }
            #pragma unroll
            for (int i = 0; i < 4; i++)
                #pragma unroll
                for (int j = 0; j < 4; j++)
                    mma_tf32(acc[i][j], a[i], b[j]);
        }
    };

    LOAD(0);
    STS(0);
    __syncthreads();

    int cur = 0;
    for (int k0 = 16; k0 < NE; k0 += 16) {
        LOAD(k0);
        MMA_STAGE(cur);
        STS(cur ^ 1);
        __syncthreads();
        cur ^= 1;
    }
    MMA_STAGE(cur);

    #pragma unroll
    for (int i = 0; i < 4; i++) {
        const int m = bm + wm * 64 + i * 16 + (lane >> 2);
        #pragma unroll
        for (int j = 0; j < 4; j++) {
            const int n = bn + wn * 32 + j * 8 + (lane & 3) * 2;
            const float b0v = bias[n], b1v = bias[n + 1];
            float2 v0 = make_float2(acc[i][j][0] + b0v, acc[i][j][1] + b1v);
            float2 v1 = make_float2(acc[i][j][2] + b0v, acc[i][j][3] + b1v);
            if (SPLIT) {
                const int b  = m >> 11;
                const int t  = m & (TT - 1);
                const int t2 = (m + 8) & (TT - 1);
                const int h  = n >> 6;
                const int d  = n & 63;
                *(float2*)&out[(((b * NH + h) * TT + t)  << 6) + d] = v0;
                *(float2*)&out[(((b * NH + h) * TT + t2) << 6) + d] = v1;
            } else {
                *(float2*)&out[m * NE + n]       = v0;
                *(float2*)&out[(m + 8) * NE + n] = v1;
            }
        }
    }
}

// ---------------------------------------------------------------------------
// Tensor-core flash attention (tf32 MMA, fp32 softmax state).
// Grid (16, NH, BB), 256 threads = 8 warps; warp w owns q rows [bm+16w, +16).
// K/V tiles of 64 keys staged in smem (tf32), register-prefetched.
// ---------------------------------------------------------------------------
__global__ __launch_bounds__(256)
void attn_tc(const float* __restrict__ Q, const float* __restrict__ K,
             const float* __restrict__ V, float* __restrict__ Y)
{
    __shared__ uint32_t Ks[64 * 68];   // stride 68: conflict-free S b-frags
    __shared__ uint32_t Vs[64 * 72];   // stride 72: conflict-free PV b-frags

    const int qt   = blockIdx.x;
    const int h    = blockIdx.y;
    const int b    = blockIdx.z;
    const int bm   = qt * 128;
    const int tid  = threadIdx.x;
    const int lane = tid & 31;
    const int w    = tid >> 5;
    const int ls   = lane >> 2;     // 0..7
    const int lc   = lane & 3;      // 0..3
    const int base = (b * NH + h) * TT;
    const int wrow = bm + w * 16;   // warp's first q row

    // Q fragments: resident in registers, scaled, tf32
    const float SC = 0.125f * 1.44269504f;   // 1/sqrt(64) * log2(e)
    uint32_t aq[8][4];
    {
        const float* q0 = Q + (base + wrow + ls) * DK;
        const float* q1 = q0 + 8 * DK;
        #pragma unroll
        for (int kk = 0; kk < 8; kk++) {
            aq[kk][0] = f2tf(q0[kk * 8 + lc]     * SC);
            aq[kk][1] = f2tf(q1[kk * 8 + lc]     * SC);
            aq[kk][2] = f2tf(q0[kk * 8 + 4 + lc] * SC);
            aq[kk][3] = f2tf(q1[kk * 8 + 4 + lc] * SC);
        }
    }

    float o[8][4] = {};
    float m0 = -1e30f, m1 = -1e30f;
    float l0 = 0.f,    l1 = 0.f;

    // cooperative tile-load geometry: thread -> (row, 16-col strip)
    const int ldrow = tid >> 2;
    const int ldcol = (tid & 3) * 16;

    const int nkb = 2 * qt + 2;

    // register prefetch of tile 0
    float4 kreg[4], vreg[4];
    {
        const float4* kp = (const float4*)&K[(base + ldrow) * DK + ldcol];
        const float4* vp = (const float4*)&V[(base + ldrow) * DK + ldcol];
        #pragma unroll
        for (int i = 0; i < 4; i++) { kreg[i] = kp[i]; vreg[i] = vp[i]; }
    }

    for (int kb = 0; kb < nkb; kb++) {
        __syncthreads();
        // store prefetched tile to smem (tf32)
        #pragma unroll
        for (int i = 0; i < 4; i++) {
            uint32_t* kd = &Ks[ldrow * 68 + ldcol + i * 4];
            kd[0] = f2tf(kreg[i].x); kd[1] = f2tf(kreg[i].y);
            kd[2] = f2tf(kreg[i].z); kd[3] = f2tf(kreg[i].w);
            uint32_t* vd = &Vs[ldrow * 72 + ldcol + i * 4];
            vd[0] = f2tf(vreg[i].x); vd[1] = f2tf(vreg[i].y);
            vd[2] = f2tf(vreg[i].z); vd[3] = f2tf(vreg[i].w);
        }
        __syncthreads();

        // prefetch next tile (LDG latency overlaps compute below)
        if (kb + 1 < nkb) {
            const float4* kp = (const float4*)&K[(base + (kb + 1) * 64 + ldrow) * DK + ldcol];
            const float4* vp = (const float4*)&V[(base + (kb + 1) * 64 + ldrow) * DK + ldcol];
            #pragma unroll
            for (int i = 0; i < 4; i++) { kreg[i] = kp[i]; vreg[i] = vp[i]; }
        }

        if (kb * 64 > wrow + 15) continue;   // whole warp slab masked

        // ---- S = Q K^T : 16 x 64 per warp ----
        float s[8][4];
        #pragma unroll
        for (int j = 0; j < 8; j++)
            s[j][0] = s[j][1] = s[j][2] = s[j][3] = 0.f;

        #pragma unroll
        for (int kk = 0; kk < 8; kk++) {
            #pragma unroll
            for (int j = 0; j < 8; j++) {
                uint32_t bb[2];
                bb[0] = Ks[(j * 8 + ls) * 68 + kk * 8 + lc];
                bb[1] = Ks[(j * 8 + ls) * 68 + kk * 8 + 4 + lc];
                mma_tf32(s[j], aq[kk], bb);
            }
        }

        const int row0 = wrow + ls;
        const int row1 = row0 + 8;

        // ---- causal mask (only diagonal tiles trigger) ----
        if (kb * 64 + 63 > row0) {
            #pragma unroll
            for (int j = 0; j < 8; j++) {
                const int col = kb * 64 + j * 8 + lc * 2;
                if (col     > row0) s[j][0] = -1e30f;
                if (col + 1 > row0) s[j][1] = -1e30f;
                if (col     > row1) s[j][2] = -1e30f;
                if (col + 1 > row1) s[j][3] = -1e30f;
            }
        }

        // ---- online softmax ----
        float mx0 = -1e30f, mx1 = -1e30f;
        #pragma unroll
        for (int j = 0; j < 8; j++) {
            mx0 = fmaxf(mx0, fmaxf(s[j][0], s[j][1]));
            mx1 = fmaxf(mx1, fmaxf(s[j][2], s[j][3]));
        }
        mx0 = fmaxf(mx0, __shfl_xor_sync(0xffffffffu, mx0, 1));
        mx0 = fmaxf(mx0, __shfl_xor_sync(0xffffffffu, mx0, 2));
        mx1 = fmaxf(mx1, __shfl_xor_sync(0xffffffffu, mx1, 1));
        mx1 = fmaxf(mx1, __shfl_xor_sync(0xffffffffu, mx1, 2));

        const float mn0 = fmaxf(m0, mx0);
        const float mn1 = fmaxf(m1, mx1);
        const float cr0 = ex2(m0 - mn0);
        const float cr1 = ex2(m1 - mn1);
        m0 = mn0; m1 = mn1;
        l0 *= cr0; l1 *= cr1;

        float ps0 = 0.f, ps1 = 0.f;
        #pragma unroll
        for (int j = 0; j < 8; j++) {
            o[j][0] *= cr0; o[j][1] *= cr0;
            o[j][2] *= cr1; o[j][3] *= cr1;
            float p0 = ex2(s[j][0] - mn0);
            float p1 = ex2(s[j][1] - mn0);
            float p2 = ex2(s[j][2] - mn1);
            float p3 = ex2(s[j][3] - mn1);
            ps0 += p0 + p1;
            ps1 += p2 + p3;
            // store tf32 bits back into the float regs
            s[j][0] = __uint_as_float(f2tf(p0));
            s[j][1] = __uint_as_float(f2tf(p1));
            s[j][2] = __uint_as_float(f2tf(p2));
            s[j][3] = __uint_as_float(f2tf(p3));
        }
        l0 += ps0; l1 += ps1;

        // ---- O += P V ----
        const int srcA = (lane & ~3) | (lc >> 1);
        const int srcB = srcA + 2;
        const bool odd = lane & 1;
        #pragma unroll
        for (int kk = 0; kk < 8; kk++) {
            // convert P C-fragment (cols 2lc,2lc+1) -> A-fragment (cols lc, lc+4)
            float v00 = __shfl_sync(0xffffffffu, s[kk][0], srcA);
            float v01 = __shfl_sync(0xffffffffu, s[kk][1], srcA);
            float v10 = __shfl_sync(0xffffffffu, s[kk][2], srcA);
            float v11 = __shfl_sync(0xffffffffu, s[kk][3], srcA);
            float w00 = __shfl_sync(0xffffffffu, s[kk][0], srcB);
            float w01 = __shfl_sync(0xffffffffu, s[kk][1], srcB);
            float w10 = __shfl_sync(0xffffffffu, s[kk][2], srcB);
            float w11 = __shfl_sync(0xffffffffu, s[kk][3], srcB);
            uint32_t a[4];
            a[0] = __float_as_uint(odd ? v01 : v00);
            a[1] = __float_as_uint(odd ? v11 : v10);
            a[2] = __float_as_uint(odd ? w01 : w00);
            a[3] = __float_as_uint(odd ? w11 : w10);
            #pragma unroll
            for (int j = 0; j < 8; j++) {
                uint32_t bb[2];
                bb[0] = Vs[(kk * 8 + lc) * 72 + j * 8 + ls];
                bb[1] = Vs[(kk * 8 + 4 + lc) * 72 + j * 8 + ls];
                mma_tf32(o[j], a, bb);
            }
        }
    }

    // final l reduction across quad + normalize + store
    l0 += __shfl_xor_sync(0xffffffffu, l0, 1);
    l0 += __shfl_xor_sync(0xffffffffu, l0, 2);
    l1 += __shfl_xor_sync(0xffffffffu, l1, 1);
    l1 += __shfl_xor_sync(0xffffffffu, l1, 2);
    const float i0 = 1.f / l0;
    const float i1 = 1.f / l1;

    const int row0 = wrow + ls;
    float* y0 = Y + (b * TT + row0)     * NE + h * DK;
    float* y1 = Y + (b * TT + row0 + 8) * NE + h * DK;
    #pragma unroll
    for (int j = 0; j < 8; j++) {
        *(float2*)&y0[j * 8 + lc * 2] = make_float2(o[j][0] * i0, o[j][1] * i0);
        *(float2*)&y1[j * 8 + lc * 2] = make_float2(o[j][2] * i1, o[j][3] * i1);
    }
}

// ---------------------------------------------------------------------------
extern "C" void kernel_launch(void* const* d_in, const int* in_sizes, int n_in,
                              void* d_out, int out_size)
{
    const float* x  = (const float*)d_in[0];
    const float* Wq = (const float*)d_in[1];
    const float* bq = (const float*)d_in[2];
    const float* Wk = (const float*)d_in[3];
    const float* bk = (const float*)d_in[4];
    const float* Wv = (const float*)d_in[5];
    const float* bv = (const float*)d_in[6];
    const float* Wo = (const float*)d_in[7];
    const float* bo = (const float*)d_in[8];
    float* out = (float*)d_out;

    float *q, *k, *v, *y;
    cudaGetSymbolAddress((void**)&q, g_q);
    cudaGetSymbolAddress((void**)&k, g_k);
    cudaGetSymbolAddress((void**)&v, g_v);
    cudaGetSymbolAddress((void**)&y, g_y);

    dim3 blk(256);
    dim3 gproj(NE / 128, MTOT / 128);  // (8, 32)

    linear_tc<true><<<gproj, blk>>>(x, Wq, bq, q);
    linear_tc<true><<<gproj, blk>>>(x, Wk, bk, k);
    linear_tc<true><<<gproj, blk>>>(x, Wv, bv, v);

    attn_tc<<<dim3(TT / 128, NH, BB), 256>>>(q, k, v, y);

    linear_tc<false><<<gproj, blk>>>(y, Wo, bo, out);
}